// round 16
// baseline (speedup 1.0000x reference)
#include <cuda_runtime.h>
#include <cuda_fp16.h>
#include <math.h>
#include <stdint.h>

#define D_MODEL 2048
#define N_HEADS 16
#define D_HEAD  128
#define BATCH   2
#define SEQ     2048
#define M_TOT   (BATCH*SEQ)      /* 4096 */
#define NQKV    (3*D_MODEL)      /* 6144 */
#define EPSF    1e-6f

// ---------------- scratch (device globals; no allocs allowed) ----------------
__device__ __half g_xh[(size_t)M_TOT * D_MODEL];
__device__ __half g_xl[(size_t)M_TOT * D_MODEL];
__device__ __half g_wqkvh[(size_t)NQKV * D_MODEL];
__device__ __half g_wqkvl[(size_t)NQKV * D_MODEL];
__device__ __half g_woh[(size_t)D_MODEL * D_MODEL];
__device__ __half g_zh[(size_t)M_TOT * D_MODEL];

__device__ __half g_qh[(size_t)M_TOT * D_MODEL];
__device__ __half g_ql[(size_t)M_TOT * D_MODEL];
__device__ __half g_kh[(size_t)M_TOT * D_MODEL];
__device__ __half g_kl[(size_t)M_TOT * D_MODEL];
__device__ __half g_vh[(size_t)M_TOT * D_MODEL];

// ---------------- helpers ----------------------------------------------------
__device__ __forceinline__ uint32_t smem_u32(const void* p) {
    uint32_t a;
    asm("{ .reg .u64 t; cvta.to.shared.u64 t, %1; cvt.u32.u64 %0, t; }"
        : "=r"(a) : "l"(p));
    return a;
}

#define MMA(c, a, b) \
    asm volatile("mma.sync.aligned.m16n8k16.row.col.f32.f16.f16.f32 " \
                 "{%0,%1,%2,%3},{%4,%5,%6,%7},{%8,%9},{%0,%1,%2,%3};" \
                 : "+f"((c)[0]), "+f"((c)[1]), "+f"((c)[2]), "+f"((c)[3]) \
                 : "r"((a)[0]), "r"((a)[1]), "r"((a)[2]), "r"((a)[3]), \
                   "r"((b)[0]), "r"((b)[1]))

#define CPA16(dst, src) \
    asm volatile("cp.async.cg.shared.global [%0], [%1], 16;" :: "r"(dst), "l"(src))

#define LDSM4(r0_, r1_, r2_, r3_, a_) \
    asm volatile("ldmatrix.sync.aligned.m8n8.x4.shared.b16 {%0,%1,%2,%3},[%4];" \
                 : "=r"(r0_), "=r"(r1_), "=r"(r2_), "=r"(r3_) : "r"(a_))

#define LDSM4T(r0_, r1_, r2_, r3_, a_) \
    asm volatile("ldmatrix.sync.aligned.m8n8.x4.trans.shared.b16 {%0,%1,%2,%3},[%4];" \
                 : "=r"(r0_), "=r"(r1_), "=r"(r2_), "=r"(r3_) : "r"(a_))

// ---------------- fused fp32 -> fp16 conversion (one launch, MLP=4) ----------
#define N4X (M_TOT*D_MODEL/4)
#define N4W (NQKV*D_MODEL/4)
#define N4O (D_MODEL*D_MODEL/4)
#define BX4 (N4X/1024)
#define BW4 (N4W/1024)
#define BO4 (N4O/1024)

__global__ __launch_bounds__(256) void conv_all(
    const float* __restrict__ x, const float* __restrict__ wqkv,
    const float* __restrict__ wo)
{
    const int bid = blockIdx.x;
    const float* src;
    __half *hi, *lo;
    int base;
    if (bid < BX4) {
        base = bid * 1024; src = x; hi = g_xh; lo = g_xl;
    } else if (bid < BX4 + BW4) {
        base = (bid - BX4) * 1024; src = wqkv; hi = g_wqkvh; lo = g_wqkvl;
    } else {
        base = (bid - BX4 - BW4) * 1024; src = wo; hi = g_woh; lo = nullptr;
    }
    #pragma unroll
    for (int j = 0; j < 4; ++j) {
        const int i = base + j * 256 + threadIdx.x;
        float4 v = ((const float4*)src)[i];
        __half2 h01, h23;
        h01.x = __float2half_rn(v.x); h01.y = __float2half_rn(v.y);
        h23.x = __float2half_rn(v.z); h23.y = __float2half_rn(v.w);
        ((__half2*)hi)[i*2]   = h01;
        ((__half2*)hi)[i*2+1] = h23;
        if (lo) {
            __half2 l01, l23;
            l01.x = __float2half_rn(v.x - __half2float(h01.x));
            l01.y = __float2half_rn(v.y - __half2float(h01.y));
            l23.x = __float2half_rn(v.z - __half2float(h23.x));
            l23.y = __float2half_rn(v.w - __half2float(h23.y));
            ((__half2*)lo)[i*2]   = l01;
            ((__half2*)lo)[i*2+1] = l23;
        }
    }
}

// ---------------- HMMA split-fp16 GEMM (per-CTA 1/2/3-pass) ------------------
// C[M,N] = A[M,K]*B[N,K]^T + bias.
// npass = bn<n3 ? 3 : (bn<n2 ? 2 : 1).
//   pass1: Ah*Bh   pass2: +Al*Bh   pass3: +Ah*Bl
// Tile slots per stage: 0=Ah, 1=Bh, 2=Al, 3=Bl (1-pass loads only 0,1).
// fuse=1 (qkv): rms-norm epilogue writing q/k/v operands + k_out/v_out.
#define TILE_E 5120
#define GEMM_SMEM_QKV (2*4*TILE_E*2)   /* 81920 B */
#define GEMM_SMEM_OP  (3*2*TILE_E*2)   /* 61440 B */

template<int NST, int NTILES>
__global__ __launch_bounds__(256, 2) void gemm_tc(
    const __half* __restrict__ pAh, const __half* __restrict__ pAl,
    const __half* __restrict__ pBh, const __half* __restrict__ pBl,
    const float* __restrict__ bias, float* __restrict__ C,
    int N, int K, int n3, int n2, int fuse,
    float* __restrict__ k_out, float* __restrict__ v_out,
    const float* __restrict__ wq, const float* __restrict__ wk)
{
    extern __shared__ __half sm[];
    const int tid = threadIdx.x, lane = tid & 31, wid = tid >> 5;
    const int wm = wid >> 1, wn = wid & 1;
    const int bm = blockIdx.y * 128, bn = blockIdx.x * 128;
    const int npass = (bn < n3) ? 3 : ((bn < n2) ? 2 : 1);
    const bool p2 = npass >= 2, p3 = npass == 3;
    const uint32_t smb = smem_u32(sm);

    const int rr = lane & 7, sub = lane >> 3;
    const int l3 = lane & 3, l4 = lane >> 2;
    const uint32_t offA = (uint32_t)((rr + (sub & 1) * 8) * 80 + (sub >> 1) * 16);
    const uint32_t offB = (uint32_t)((rr + (sub >> 1) * 8) * 80 + (sub & 1) * 16);

    float acc[2][8][4];
    #pragma unroll
    for (int mt = 0; mt < 2; ++mt)
        #pragma unroll
        for (int nt = 0; nt < 8; ++nt)
            #pragma unroll
            for (int j = 0; j < 4; ++j) acc[mt][nt][j] = 0.f;

    const int nch = K / 32;
    const __half* srcs[4] = {
        pAh + (size_t)bm * K, pBh + (size_t)bn * K,
        pAl + (size_t)bm * K, pBl + (size_t)bn * K };
    const int ntl = npass + 1;

    const int lrow = tid >> 2, lcc = tid & 3;
    const int lrow2 = (tid + 256) >> 2;

    #define ISSUE(st_, ch_) do {                                           \
        const int _k0 = (ch_) * 32;                                        \
        for (int _t = 0; _t < ntl; ++_t) {                                 \
            const __half* _s0 = srcs[_t] + _k0 + lcc * 8;                  \
            uint32_t _d0 = smb + (uint32_t)(((st_)*NTILES + _t) * (TILE_E*2)); \
            const void* _sp1 = _s0 + (size_t)lrow * K;                     \
            uint32_t _dp1 = _d0 + (uint32_t)(lrow * 80 + lcc * 16);        \
            CPA16(_dp1, _sp1);                                             \
            const void* _sp2 = _s0 + (size_t)lrow2 * K;                    \
            uint32_t _dp2 = _d0 + (uint32_t)(lrow2 * 80 + lcc * 16);       \
            CPA16(_dp2, _sp2);                                             \
        }                                                                  \
        asm volatile("cp.async.commit_group;" ::: "memory");               \
    } while (0)

    #define K16_BLOCK(cb_) do {                                            \
        const uint32_t cb = (uint32_t)(cb_);                               \
        uint32_t ah[2][4], al[2][4], bh[8][2], bl[8][2];                   \
        _Pragma("unroll")                                                  \
        for (int mt = 0; mt < 2; ++mt)                                     \
            LDSM4(ah[mt][0], ah[mt][1], ah[mt][2], ah[mt][3],              \
                  aBase + (uint32_t)(mt * 1280) + cb);                     \
        _Pragma("unroll")                                                  \
        for (int p = 0; p < 4; ++p)                                        \
            LDSM4(bh[2*p][0], bh[2*p][1], bh[2*p+1][0], bh[2*p+1][1],      \
                  bBase + (uint32_t)(p * 1280) + cb);                      \
        if (p2) {                                                          \
            _Pragma("unroll")                                              \
            for (int mt = 0; mt < 2; ++mt)                                 \
                LDSM4(al[mt][0], al[mt][1], al[mt][2], al[mt][3],          \
                      alBase + (uint32_t)(mt * 1280) + cb);                \
        }                                                                  \
        if (p3) {                                                          \
            _Pragma("unroll")                                              \
            for (int p = 0; p < 4; ++p)                                    \
                LDSM4(bl[2*p][0], bl[2*p][1], bl[2*p+1][0], bl[2*p+1][1],  \
                      blBase + (uint32_t)(p * 1280) + cb);                 \
        }                                                                  \
        _Pragma("unroll")                                                  \
        for (int mt = 0; mt < 2; ++mt)                                     \
            _Pragma("unroll")                                              \
            for (int nt = 0; nt < 8; ++nt)                                 \
                MMA(acc[mt][nt], ah[mt], bh[nt]);                          \
        if (p2) {                                                          \
            _Pragma("unroll")                                              \
            for (int mt = 0; mt < 2; ++mt)                                 \
                _Pragma("unroll")                                          \
                for (int nt = 0; nt < 8; ++nt)                             \
                    MMA(acc[mt][nt], al[mt], bh[nt]);                      \
        }                                                                  \
        if (p3) {                                                          \
            _Pragma("unroll")                                              \
            for (int mt = 0; mt < 2; ++mt)                                 \
                _Pragma("unroll")                                          \
                for (int nt = 0; nt < 8; ++nt)                             \
                    MMA(acc[mt][nt], ah[mt], bl[nt]);                      \
        }                                                                  \
    } while (0)

    ISSUE(0, 0);
    if (NST == 3 && nch > 1) ISSUE(1, 1);

    int st = 0;
    int ist = (NST - 1) % NST;
    for (int ch = 0; ch < nch; ++ch) {
        if (NST == 2) {
            asm volatile("cp.async.wait_group 0;" ::: "memory");
        } else {
            if (ch + 1 < nch) asm volatile("cp.async.wait_group 1;" ::: "memory");
            else              asm volatile("cp.async.wait_group 0;" ::: "memory");
        }
        __syncthreads();

        const uint32_t stbase = smb + (uint32_t)(st * (NTILES * TILE_E * 2));
        const uint32_t aBase  = stbase + (uint32_t)(wm * 32 * 80) + offA;
        const uint32_t bBase  = stbase + (uint32_t)(1 * TILE_E * 2) +
                                (uint32_t)(wn * 64 * 80) + offB;
        const uint32_t alBase = stbase + (uint32_t)(2 * TILE_E * 2) +
                                (uint32_t)(wm * 32 * 80) + offA;
        const uint32_t blBase = stbase + (uint32_t)(3 * TILE_E * 2) +
                                (uint32_t)(wn * 64 * 80) + offB;

        K16_BLOCK(0);
        if (ch + NST - 1 < nch) ISSUE(ist, ch + NST - 1);
        K16_BLOCK(32);

        if (++st == NST) st = 0;
        if (++ist == NST) ist = 0;
    }

    // ---- add bias ----
    #pragma unroll
    for (int mt = 0; mt < 2; ++mt)
        #pragma unroll
        for (int nt = 0; nt < 8; ++nt) {
            const int cbl = wn * 64 + nt * 8 + l3 * 2;
            const float b0 = bias[bn + cbl], b1 = bias[bn + cbl + 1];
            acc[mt][nt][0] += b0; acc[mt][nt][1] += b1;
            acc[mt][nt][2] += b0; acc[mt][nt][3] += b1;
        }

    if (!fuse) {
        #pragma unroll
        for (int mt = 0; mt < 2; ++mt) {
            const int r1 = bm + wm * 32 + mt * 16 + l4;
            const int r2 = r1 + 8;
            #pragma unroll
            for (int nt = 0; nt < 8; ++nt) {
                const int cbg = bn + wn * 64 + nt * 8 + l3 * 2;
                float2 o1, o2;
                o1.x = acc[mt][nt][0]; o1.y = acc[mt][nt][1];
                o2.x = acc[mt][nt][2]; o2.y = acc[mt][nt][3];
                *(float2*)&C[(size_t)r1 * N + cbg] = o1;
                *(float2*)&C[(size_t)r2 * N + cbg] = o2;
            }
        }
        return;
    }

    // ---- fused qkv epilogue: tile = one head ----
    const int kind = (bn < D_MODEL) ? 0 : (bn < 2*D_MODEL ? 1 : 2);

    if (kind == 2) {
        #pragma unroll
        for (int mt = 0; mt < 2; ++mt) {
            const int r1 = bm + wm * 32 + mt * 16 + l4;
            const int r2 = r1 + 8;
            #pragma unroll
            for (int nt = 0; nt < 8; ++nt) {
                const int col = (bn - 2*D_MODEL) + wn * 64 + nt * 8 + l3 * 2;
                float2 o1, o2;
                o1.x = acc[mt][nt][0]; o1.y = acc[mt][nt][1];
                o2.x = acc[mt][nt][2]; o2.y = acc[mt][nt][3];
                *(float2*)&v_out[(size_t)r1 * D_MODEL + col] = o1;
                *(float2*)&v_out[(size_t)r2 * D_MODEL + col] = o2;
                __half2 h1, h2;
                h1.x = __float2half_rn(o1.x); h1.y = __float2half_rn(o1.y);
                h2.x = __float2half_rn(o2.x); h2.y = __float2half_rn(o2.y);
                *(__half2*)&g_vh[(size_t)r1 * D_MODEL + col] = h1;
                *(__half2*)&g_vh[(size_t)r2 * D_MODEL + col] = h2;
            }
        }
        return;
    }

    // q or k: rms-norm across the tile's 128 cols
    __syncthreads();
    float* rsum = (float*)sm;
    float ss[2][2] = {{0.f,0.f},{0.f,0.f}};
    #pragma unroll
    for (int mt = 0; mt < 2; ++mt)
        #pragma unroll
        for (int nt = 0; nt < 8; ++nt) {
            ss[mt][0] += acc[mt][nt][0]*acc[mt][nt][0] + acc[mt][nt][1]*acc[mt][nt][1];
            ss[mt][1] += acc[mt][nt][2]*acc[mt][nt][2] + acc[mt][nt][3]*acc[mt][nt][3];
        }
    #pragma unroll
    for (int mt = 0; mt < 2; ++mt)
        #pragma unroll
        for (int hf = 0; hf < 2; ++hf) {
            ss[mt][hf] += __shfl_xor_sync(0xffffffffu, ss[mt][hf], 1);
            ss[mt][hf] += __shfl_xor_sync(0xffffffffu, ss[mt][hf], 2);
        }
    if (l3 == 0) {
        #pragma unroll
        for (int mt = 0; mt < 2; ++mt) {
            rsum[wn*128 + wm*32 + mt*16 + l4]     = ss[mt][0];
            rsum[wn*128 + wm*32 + mt*16 + l4 + 8] = ss[mt][1];
        }
    }
    __syncthreads();

    const float* wv = (kind == 0) ? wq : wk;
    __half* dst_h = (kind == 0) ? g_qh : g_kh;
    __half* dst_l = (kind == 0) ? g_ql : g_kl;
    const int colbase = (kind == 0) ? bn : bn - D_MODEL;

    #pragma unroll
    for (int mt = 0; mt < 2; ++mt) {
        const int rl1 = wm*32 + mt*16 + l4;
        const int rl2 = rl1 + 8;
        const float fac1 = rsqrtf((rsum[rl1] + rsum[128 + rl1]) * (1.f/128.f) + EPSF);
        const float fac2 = rsqrtf((rsum[rl2] + rsum[128 + rl2]) * (1.f/128.f) + EPSF);
        const int r1 = bm + rl1, r2 = bm + rl2;
        #pragma unroll
        for (int nt = 0; nt < 8; ++nt) {
            const int cbl = wn * 64 + nt * 8 + l3 * 2;
            const int col = colbase + cbl;
            if (kind == 1) {
                float2 o1, o2;
                o1.x = acc[mt][nt][0]; o1.y = acc[mt][nt][1];
                o2.x = acc[mt][nt][2]; o2.y = acc[mt][nt][3];
                *(float2*)&k_out[(size_t)r1 * D_MODEL + col] = o1;
                *(float2*)&k_out[(size_t)r2 * D_MODEL + col] = o2;
            }
            const float w0 = wv[cbl], w1 = wv[cbl + 1];
            const float n0 = acc[mt][nt][0] * fac1 * w0;
            const float n1 = acc[mt][nt][1] * fac1 * w1;
            const float n2 = acc[mt][nt][2] * fac2 * w0;
            const float n3v = acc[mt][nt][3] * fac2 * w1;
            __half2 h1, h2, lo1, lo2;
            h1.x = __float2half_rn(n0);  h1.y = __float2half_rn(n1);
            h2.x = __float2half_rn(n2);  h2.y = __float2half_rn(n3v);
            lo1.x = __float2half_rn(n0 - __half2float(h1.x));
            lo1.y = __float2half_rn(n1 - __half2float(h1.y));
            lo2.x = __float2half_rn(n2 - __half2float(h2.x));
            lo2.y = __float2half_rn(n3v - __half2float(h2.y));
            *(__half2*)&dst_h[(size_t)r1 * D_MODEL + col] = h1;
            *(__half2*)&dst_l[(size_t)r1 * D_MODEL + col] = lo1;
            *(__half2*)&dst_h[(size_t)r2 * D_MODEL + col] = h2;
            *(__half2*)&dst_l[(size_t)r2 * D_MODEL + col] = lo2;
        }
    }
}

// --------------- flash attention: BQ=128, double-buffered K/V ----------------
// S 3-pass; PV 1-pass (P fp16-rn, l in fp32); z stored hi-only.
#define AT_STRIDE 136
#define KV_TILE_B (64*AT_STRIDE*2)
#define QT_TILE_B (128*AT_STRIDE*2)
#define KV_STG_B  (3*KV_TILE_B)
#define KV_BASE_B (2*QT_TILE_B)
#define ATT_SMEM  (KV_BASE_B + 2*KV_STG_B)  /* 174080 B */

__global__ __launch_bounds__(256, 1) void attn_tc()
{
    extern __shared__ __half smb[];
    const int tid = threadIdx.x, lane = tid & 31, wid = tid >> 5;
    const int l3 = lane & 3, l4 = lane >> 2;
    const int rr = lane & 7, sub = lane >> 3;
    const int qt = blockIdx.x;
    const int bh = blockIdx.y;
    const int b = bh >> 4, h = bh & 15;
    const size_t qmbase = (size_t)b * SEQ + qt * 128;
    const size_t kmbase = (size_t)b * SEQ;
    const int colbase = h * D_HEAD;

    const uint32_t smbase = smem_u32(smb);

    const uint32_t offA  = (uint32_t)((rr + (sub & 1) * 8) * 272 + (sub >> 1) * 16);
    const uint32_t offB  = (uint32_t)((rr + (sub >> 1) * 8) * 272 + (sub & 1) * 16);

    // ---- load Q tile (hi+lo, 128 rows) ----
    {
        const __half* gq = g_qh + qmbase * D_MODEL + colbase;
        const __half* gl = g_ql + qmbase * D_MODEL + colbase;
        #pragma unroll
        for (int it = 0; it < 8; ++it) {
            const int c = it * 256 + tid;
            const int row = c >> 4, c16 = c & 15;
            const uint32_t dst = smbase + (uint32_t)(row * 272 + c16 * 16);
            CPA16(dst,             gq + (size_t)row * D_MODEL + c16 * 8);
            CPA16(dst + QT_TILE_B, gl + (size_t)row * D_MODEL + c16 * 8);
        }
        asm volatile("cp.async.commit_group;" ::: "memory");
    }
    // ---- load KV stage 0 ----
    {
        const size_t mrow = kmbase * D_MODEL + colbase;
        #pragma unroll
        for (int it = 0; it < 4; ++it) {
            const int c = it * 256 + tid;
            const int row = c >> 4, c16 = c & 15;
            const size_t so = (size_t)row * D_MODEL + c16 * 8;
            const uint32_t dst = smbase + (uint32_t)(KV_BASE_B + row * 272 + c16 * 16);
            CPA16(dst,                 g_kh + mrow + so);
            CPA16(dst + KV_TILE_B,     g_kl + mrow + so);
            CPA16(dst + 2*KV_TILE_B,   g_vh + mrow + so);
        }
        asm volatile("cp.async.commit_group;" ::: "memory");
    }
    asm volatile("cp.async.wait_group 0;" ::: "memory");
    __syncthreads();

    float O[16][4];
    #pragma unroll
    for (int nt = 0; nt < 16; ++nt)
        #pragma unroll
        for (int j = 0; j < 4; ++j) O[nt][j] = 0.f;
    float m0 = -1e30f, m1 = -1e30f, l0 = 0.f, l1 = 0.f;

    const uint32_t qBaseH = smbase + (uint32_t)(wid * 16 * 272) + offA;
    const uint32_t qBaseL = qBaseH + QT_TILE_B;

    for (int kt = 0; kt < SEQ/64; ++kt) {
        const int st = kt & 1;
        const uint32_t kBaseH = smbase + (uint32_t)(KV_BASE_B + st * KV_STG_B) + offB;
        const uint32_t kBaseL = kBaseH + KV_TILE_B;
        const uint32_t vBaseH = smbase + (uint32_t)(KV_BASE_B + st * KV_STG_B + 2*KV_TILE_B) + offA;

        // ---- S = Qn Kn^T, 3-pass ----
        float s[8][4];
        #pragma unroll
        for (int nt = 0; nt < 8; ++nt)
            #pragma unroll
            for (int j = 0; j < 4; ++j) s[nt][j] = 0.f;

        #pragma unroll
        for (int ks = 0; ks < 8; ++ks) {
            const uint32_t cb = (uint32_t)(ks * 32);
            uint32_t ah[4], al[4], bh2[8][2], bl2[8][2];
            LDSM4(ah[0], ah[1], ah[2], ah[3], qBaseH + cb);
            LDSM4(al[0], al[1], al[2], al[3], qBaseL + cb);
            #pragma unroll
            for (int p = 0; p < 4; ++p) {
                LDSM4(bh2[2*p][0], bh2[2*p][1], bh2[2*p+1][0], bh2[2*p+1][1],
                      kBaseH + (uint32_t)(p * 16 * 272) + cb);
                LDSM4(bl2[2*p][0], bl2[2*p][1], bl2[2*p+1][0], bl2[2*p+1][1],
                      kBaseL + (uint32_t)(p * 16 * 272) + cb);
            }
            #pragma unroll
            for (int nt = 0; nt < 8; ++nt)
                MMA(s[nt], ah, bh2[nt]);
            #pragma unroll
            for (int nt = 0; nt < 8; ++nt)
                MMA(s[nt], ah, bl2[nt]);
            #pragma unroll
            for (int nt = 0; nt < 8; ++nt)
                MMA(s[nt], al, bh2[nt]);
        }

        // ---- prefetch next KV ----
        if (kt + 1 < SEQ/64) {
            const size_t mrow = (kmbase + (kt + 1) * 64) * D_MODEL + colbase;
            const uint32_t sb = (uint32_t)(KV_BASE_B + (st ^ 1) * KV_STG_B);
            #pragma unroll
            for (int it = 0; it < 4; ++it) {
                const int c = it * 256 + tid;
                const int row = c >> 4, c16 = c & 15;
                const size_t so = (size_t)row * D_MODEL + c16 * 8;
                const uint32_t dst = smbase + sb + (uint32_t)(row * 272 + c16 * 16);
                CPA16(dst,               g_kh + mrow + so);
                CPA16(dst + KV_TILE_B,   g_kl + mrow + so);
                CPA16(dst + 2*KV_TILE_B, g_vh + mrow + so);
            }
            asm volatile("cp.async.commit_group;" ::: "memory");
        }

        // ---- online softmax (P -> fp16 hi only; l summed in fp32) ----
        float mx0 = -1e30f, mx1 = -1e30f;
        #pragma unroll
        for (int nt = 0; nt < 8; ++nt) {
            mx0 = fmaxf(mx0, fmaxf(s[nt][0], s[nt][1]));
            mx1 = fmaxf(mx1, fmaxf(s[nt][2], s[nt][3]));
        }
        mx0 = fmaxf(mx0, __shfl_xor_sync(0xffffffffu, mx0, 1));
        mx0 = fmaxf(mx0, __shfl_xor_sync(0xffffffffu, mx0, 2));
        mx1 = fmaxf(mx1, __shfl_xor_sync(0xffffffffu, mx1, 1));
        mx1 = fmaxf(mx1, __shfl_xor_sync(0xffffffffu, mx1, 2));
        const float mn0 = fmaxf(m0, mx0), mn1 = fmaxf(m1, mx1);
        const float corr0 = __expf(m0 - mn0), corr1 = __expf(m1 - mn1);
        m0 = mn0; m1 = mn1;

        uint32_t ph[8][2];
        float rs0 = 0.f, rs1 = 0.f;
        #pragma unroll
        for (int nt = 0; nt < 8; ++nt) {
            float p0 = __expf(s[nt][0] - mn0);
            float p1 = __expf(s[nt][1] - mn0);
            float p2 = __expf(s[nt][2] - mn1);
            float p3 = __expf(s[nt][3] - mn1);
            rs0 += p0 + p1; rs1 += p2 + p3;
            __half2 h01, h23;
            h01.x = __float2half_rn(p0); h01.y = __float2half_rn(p1);
            h23.x = __float2half_rn(p2); h23.y = __float2half_rn(p3);
            ph[nt][0] = *(uint32_t*)&h01;  ph[nt][1] = *(uint32_t*)&h23;
        }
        rs0 += __shfl_xor_sync(0xffffffffu, rs0, 1);
        rs0 += __shfl_xor_sync(0xffffffffu, rs0, 2);
        rs1 += __shfl_xor_sync(0xffffffffu, rs1, 1);
        rs1 += __shfl_xor_sync(0xffffffffu, rs1, 2);
        l0 = l0 * corr0 + rs0;
        l1 = l1 * corr1 + rs1;
        #pragma unroll
        for (int nt = 0; nt < 16; ++nt) {
            O[nt][0] *= corr0; O[nt][1] *= corr0;
            O[nt][2] *= corr1; O[nt][3] *= corr1;
        }

        // ---- O += Ph Vh ----
        #pragma unroll
        for (int ks = 0; ks < 4; ++ks) {
            uint32_t a_h[4] = { ph[2*ks][0], ph[2*ks][1], ph[2*ks+1][0], ph[2*ks+1][1] };
            const uint32_t krow = (uint32_t)(ks * 16 * 272);
            #pragma unroll
            for (int ntp = 0; ntp < 8; ++ntp) {
                uint32_t vh0, vh1, vh2, vh3;
                LDSM4T(vh0, vh1, vh2, vh3, vBaseH + krow + (uint32_t)(ntp * 32));
                uint32_t b0[2] = { vh0, vh1 }, b1[2] = { vh2, vh3 };
                MMA(O[2*ntp],   a_h, b0);
                MMA(O[2*ntp+1], a_h, b1);
            }
        }
        asm volatile("cp.async.wait_group 0;" ::: "memory");
        __syncthreads();
    }

    // ---- epilogue: O/l -> z fp16 (hi only) ----
    const float inv0 = 1.f / l0, inv1 = 1.f / l1;
    const size_t r0g = qmbase + wid * 16 + l4;
    const size_t r1g = r0g + 8;
    #pragma unroll
    for (int nt = 0; nt < 16; ++nt) {
        const int col = colbase + nt * 8 + 2 * l3;
        const float o0 = O[nt][0] * inv0, o1 = O[nt][1] * inv0;
        const float o2 = O[nt][2] * inv1, o3 = O[nt][3] * inv1;
        __half2 h01, h23;
        h01.x = __float2half_rn(o0); h01.y = __float2half_rn(o1);
        h23.x = __float2half_rn(o2); h23.y = __float2half_rn(o3);
        *(uint32_t*)&g_zh[r0g * D_MODEL + col] = *(uint32_t*)&h01;
        *(uint32_t*)&g_zh[r1g * D_MODEL + col] = *(uint32_t*)&h23;
    }
}

// -----------------------------------------------------------------------------
extern "C" void kernel_launch(void* const* d_in, const int* in_sizes, int n_in,
                              void* d_out, int out_size)
{
    const float* x     = (const float*)d_in[0];
    const float* W_qkv = (const float*)d_in[1];
    const float* b_qkv = (const float*)d_in[2];
    const float* W_o   = (const float*)d_in[3];
    const float* b_o   = (const float*)d_in[4];
    const float* wq    = (const float*)d_in[5];
    const float* wk    = (const float*)d_in[6];

    float* out   = (float*)d_out;
    float* k_out = out   + (size_t)M_TOT * D_MODEL;
    float* v_out = k_out + (size_t)M_TOT * D_MODEL;

    __half *xh, *xl, *wqh, *wql, *woh, *zh;
    cudaGetSymbolAddress((void**)&xh,  g_xh);
    cudaGetSymbolAddress((void**)&xl,  g_xl);
    cudaGetSymbolAddress((void**)&wqh, g_wqkvh);
    cudaGetSymbolAddress((void**)&wql, g_wqkvl);
    cudaGetSymbolAddress((void**)&woh, g_woh);
    cudaGetSymbolAddress((void**)&zh,  g_zh);

    static bool attr_set = false;
    if (!attr_set) {
        cudaFuncSetAttribute(gemm_tc<2,4>, cudaFuncAttributeMaxDynamicSharedMemorySize, GEMM_SMEM_QKV);
        cudaFuncSetAttribute(gemm_tc<3,2>, cudaFuncAttributeMaxDynamicSharedMemorySize, GEMM_SMEM_OP);
        cudaFuncSetAttribute(attn_tc, cudaFuncAttributeMaxDynamicSharedMemorySize, ATT_SMEM);
        attr_set = true;
    }

    // 0) all operand conversions in one launch (MLP=4)
    conv_all<<<BX4 + BW4 + BO4, 256>>>(x, W_qkv, W_o);

    // 1) qkv GEMM + fused rms-norm (q,k 3-pass; v 1-pass), 2-stage
    gemm_tc<2,4><<<dim3(NQKV/128, M_TOT/128), 256, GEMM_SMEM_QKV>>>(
        xh, xl, wqh, wql, b_qkv, nullptr, NQKV, D_MODEL,
        2*D_MODEL, 2*D_MODEL, 1, k_out, v_out, wq, wk);

    // 2) attention -> g_zh
    attn_tc<<<dim3(SEQ/128, BATCH*N_HEADS), 256, ATT_SMEM>>>();

    // 3) out = z @ W_o^T + b_o   (1-pass, 3-stage, 2 tiles/stage)
    gemm_tc<3,2><<<dim3(D_MODEL/128, M_TOT/128), 256, GEMM_SMEM_OP>>>(
        zh, zh, woh, woh, b_o, out, D_MODEL, D_MODEL,
        0, 0, 0, nullptr, nullptr, nullptr, nullptr);
}